// round 14
// baseline (speedup 1.0000x reference)
#include <cuda_runtime.h>
#include <cuda_fp16.h>
#include <cstdint>

#define S_   4
#define B_   256
#define Q_   1024
#define P_   32768
#define D_   256
#define NB   11
#define KOUT 10
#define NEG_INF (-1e30f)

#define PT    256           // p per CTA tile
#define NPT   128           // P_/PT
#define QT    128           // q per CTA tile
#define NQT   8             // Q_/QT
#define TOPT  8             // candidates kept per (q, ptile)
#define MSEL  32            // candidates rescored per (s',q)

// ---------------- static device scratch ----------------
__device__ float    g_qvec [Q_ * D_];
__device__ __half   g_qvech[Q_ * D_];
__device__ __half   g_enth [(size_t)S_ * P_ * D_];               // 64MB
__device__ uint32_t g_cand [(size_t)S_ * Q_ * NPT * TOPT];       // 16MB packed (mono16<<16)|p
__device__ float    g_best_sc[S_ * Q_ * NB];
__device__ int      g_best_ix[S_ * Q_ * NB];

__device__ __forceinline__ uint32_t smem_to_u32(const void* p) {
    uint32_t a;
    asm("{ .reg .u64 t; cvta.to.shared.u64 t, %1; cvt.u32.u64 %0, t; }" : "=r"(a) : "l"(p));
    return a;
}
// order-preserving f16 bits -> u16 code
__device__ __forceinline__ uint32_t mono16(uint32_t h) {
    uint32_t mask = (h & 0x8000u) ? 0xFFFFu : 0x8000u;
    return (h ^ mask) & 0xFFFFu;
}
// 16B-chunk XOR swizzle within a 512B row (32 chunks): conflict-free ldmatrix
__device__ __forceinline__ uint32_t swz(int row, int chunk) {
    int c = (chunk & ~7) | ((chunk ^ row) & 7);
    return (uint32_t)(row * 512 + c * 16);
}
__device__ __forceinline__ void cp_async16(uint32_t smem, const void* gmem) {
    asm volatile("cp.async.cg.shared.global [%0], [%1], 16;" :: "r"(smem), "l"(gmem));
}
__device__ __forceinline__ void cp_commit_wait() {
    asm volatile("cp.async.commit_group;");
    asm volatile("cp.async.wait_group 0;");
}
__device__ __forceinline__ void ldsm_x4(uint32_t* r, uint32_t addr) {
    asm volatile("ldmatrix.sync.aligned.m8n8.x4.shared.b16 {%0,%1,%2,%3}, [%4];"
                 : "=r"(r[0]), "=r"(r[1]), "=r"(r[2]), "=r"(r[3]) : "r"(addr));
}
// f16 inputs, f16 accumulation
__device__ __forceinline__ void mma16816_f16(uint32_t* d, const uint32_t* a, const uint32_t* b) {
    asm volatile(
        "mma.sync.aligned.m16n8k16.row.col.f16.f16.f16.f16 "
        "{%0,%1}, {%2,%3,%4,%5}, {%6,%7}, {%0,%1};"
        : "+r"(d[0]), "+r"(d[1])
        : "r"(a[0]), "r"(a[1]), "r"(a[2]), "r"(a[3]), "r"(b[0]), "r"(b[1]));
}

// ============================================================
// Kernel 0a: ent f32 -> f16
// ============================================================
__global__ void conv_kernel(const float* __restrict__ ent) {
    size_t i = ((size_t)blockIdx.x * blockDim.x + threadIdx.x) * 4;
    float4 v = *(const float4*)(ent + i);
    *(__half2*)(g_enth + i)     = __floats2half2_rn(v.x, v.y);
    *(__half2*)(g_enth + i + 2) = __floats2half2_rn(v.z, v.w);
}

// ============================================================
// Kernel 0b: qvec f32 + f16
// ============================================================
__global__ void qvec_kernel(const int* __restrict__ relation,
                            const int* __restrict__ head,
                            const float* __restrict__ ent,
                            const float* __restrict__ rel) {
    int q = blockIdx.x, d = threadIdx.x;
    int s = q >> 8;
    int hd = head[q], rr = relation[q];
    float v = ent[((size_t)s * P_ + hd) * D_ + d] * rel[(size_t)rr * D_ + d];
    g_qvec[q * D_ + d]  = v;
    g_qvech[q * D_ + d] = __float2half_rn(v);
}

// ============================================================
// Kernel 1: HMMA f16 score, wide warp tile 64q x 64p
// grid (8, 128, 4), block 256 (8 warps; 2x4 warp grid)
// per warp per k-step: 8 LDSM : 32 MMA  (ratio 0.25)
// smem: A 64KB @0, B 128KB @65536 (=196608 with scratch)
// epilogue overlay: sSh u32 [128][132] @0 (67584B),
//   scr packed u32 [256][8] @98304 (8KB)
// ============================================================
#define SM_B_OFF   65536
#define SM_SH_STR  132
#define SM_SCR     98304
#define SM_TOTAL   196608

__global__ __launch_bounds__(256) void score_kernel() {
    extern __shared__ char sm[];
    const uint32_t sbase = smem_to_u32(sm);
    const int tid = threadIdx.x;
    const int wid = tid >> 5, lane = tid & 31;
    const int qtile = blockIdx.x, ptile = blockIdx.y, sp = blockIdx.z;

    // ---- stage A: 128 rows x 256 f16 (4096 chunks, 16 iters) ----
    {
        const __half* src = g_qvech + (size_t)qtile * QT * D_;
        #pragma unroll
        for (int it = 0; it < 16; it++) {
            int i = tid + it * 256;
            int row = i >> 5, ch = i & 31;
            cp_async16(sbase + swz(row, ch), src + (size_t)row * D_ + ch * 8);
        }
    }
    // ---- stage B: 256 rows x 256 f16 (8192 chunks, 32 iters) ----
    {
        const __half* src = g_enth + ((size_t)sp * P_ + (size_t)ptile * PT) * D_;
        #pragma unroll
        for (int it = 0; it < 32; it++) {
            int i = tid + it * 256;
            int row = i >> 5, ch = i & 31;
            cp_async16(sbase + SM_B_OFF + swz(row, ch), src + (size_t)row * D_ + ch * 8);
        }
    }
    cp_commit_wait();
    __syncthreads();

    // ---- MMA main loop: warp tile 64q x 64p, f16 accum ----
    const int wq = wid >> 2;          // 0..1
    const int wp = wid & 3;           // 0..3
    const int q0 = wq * 64, p0 = wp * 64;
    const int arow = (lane & 15);
    const int asel = (lane >> 4);
    const int brow = ((lane >> 4) << 3) + (lane & 7);   // row within 16-row group
    const int bsel = (lane >> 3) & 1;                   // k-chunk select

    uint32_t d[4][8][2];
    #pragma unroll
    for (int mi = 0; mi < 4; mi++)
        #pragma unroll
        for (int ni = 0; ni < 8; ni++) { d[mi][ni][0] = 0u; d[mi][ni][1] = 0u; }

    #pragma unroll
    for (int ks = 0; ks < 16; ks++) {
        const int ch0 = ks * 2;
        uint32_t a[4][4], b[4][4];
        #pragma unroll
        for (int mi = 0; mi < 4; mi++)
            ldsm_x4(a[mi], sbase + swz(q0 + mi * 16 + arow, ch0 + asel));
        #pragma unroll
        for (int g = 0; g < 4; g++)
            ldsm_x4(b[g], sbase + SM_B_OFF + swz(p0 + g * 16 + brow, ch0 + bsel));
        #pragma unroll
        for (int mi = 0; mi < 4; mi++)
            #pragma unroll
            for (int ni = 0; ni < 8; ni++)
                mma16816_f16(d[mi][ni], a[mi], &b[ni >> 1][(ni & 1) * 2]);
    }
    __syncthreads();   // staged tiles dead; epilogue overlays them

    // ---- dump raw f16x2 accum words -> sSh [128][132] (u32) ----
    uint32_t* sSh = (uint32_t*)sm;
    {
        int rr = lane >> 2, cc = 2 * (lane & 3);
        #pragma unroll
        for (int mi = 0; mi < 4; mi++)
            #pragma unroll
            for (int ni = 0; ni < 8; ni++) {
                int r  = q0 + mi * 16 + rr;
                int pr = (p0 + ni * 8 + cc) >> 1;     // pair index 0..127
                sSh[r * SM_SH_STR + pr]       = d[mi][ni][0];
                sSh[(r + 8) * SM_SH_STR + pr] = d[mi][ni][1];
            }
    }
    __syncthreads();

    // ---- per-thread packed top-8 over 128 p's (64 f16x2 words) ----
    uint32_t* scr = (uint32_t*)(sm + SM_SCR);   // [256][8]
    const int tq = tid >> 1, tsg = tid & 1;
    const int pg0 = ptile * PT;
    {
        uint32_t bs[TOPT];
        #pragma unroll
        for (int r = 0; r < TOPT; r++) bs[r] = 0u;
        #pragma unroll 8
        for (int i = 0; i < 64; i++) {
            int p2 = tsg + (i << 1);                 // pair 0..127
            uint32_t u = sSh[tq * SM_SH_STR + p2];
            uint32_t v0 = (mono16(u & 0xFFFFu) << 16) | (uint32_t)(pg0 + 2 * p2);
            uint32_t v1 = (mono16(u >> 16)     << 16) | (uint32_t)(pg0 + 2 * p2 + 1);
            #pragma unroll
            for (int h = 0; h < 2; h++) {
                uint32_t v = h ? v1 : v0;
                if (v > bs[TOPT - 1]) {
                    uint32_t cv = v;
                    #pragma unroll
                    for (int r = 0; r < TOPT; r++) {
                        if (cv > bs[r]) { uint32_t t = bs[r]; bs[r] = cv; cv = t; }
                    }
                }
            }
        }
        #pragma unroll
        for (int r = 0; r < TOPT; r++)
            scr[(tq * 2 + tsg) * TOPT + r] = bs[r];
    }
    __syncthreads();

    // ---- leader: merge 2 sorted packed top-8 lists -> top-8, write ----
    if (tsg == 0) {
        int q = qtile * QT + tq;
        size_t ob = (((size_t)sp * Q_ + q) * NPT + ptile) * TOPT;
        int h0 = 0, h1 = 0;
        const uint32_t* L = scr + (size_t)tq * 2 * TOPT;
        #pragma unroll
        for (int r = 0; r < TOPT; r++) {
            uint32_t v0 = (h0 < TOPT) ? L[h0] : 0u;
            uint32_t v1 = (h1 < TOPT) ? L[TOPT + h1] : 0u;
            if (v0 >= v1) { g_cand[ob + r] = v0; h0++; }
            else          { g_cand[ob + r] = v1; h1++; }
        }
    }
}

// ============================================================
// Kernel 2: per (s',q): packed tournament over 128 sorted top-8
// lists -> approx top-32, exact f32 rescore, exact top-11.
// grid 4096, block 512
// ============================================================
__global__ __launch_bounds__(512) void select_kernel(const float* __restrict__ ent) {
    __shared__ uint32_t cp_t[TOPT][NPT];   // [rank][list] packed
    __shared__ int      sel_ix[MSEL];
    __shared__ float    fsc[MSEL];

    const int tid = threadIdx.x;
    const int pair = blockIdx.x;
    const int sp = pair >> 10, q = pair & 1023;
    size_t base = ((size_t)sp * Q_ + q) * (size_t)(NPT * TOPT);

    for (int e = tid; e < NPT * TOPT; e += 512)
        cp_t[e & 7][e >> 3] = g_cand[base + e];
    __syncthreads();

    // warp 0: tournament; lane owns 4 lists with packed register heads
    if (tid < 32) {
        int      h[4];
        uint32_t hv[4];
        #pragma unroll
        for (int j = 0; j < 4; j++) { h[j] = 0; hv[j] = cp_t[0][tid * 4 + j]; }
        for (int r = 0; r < MSEL; r++) {
            uint32_t best = hv[0]; int bj = 0;
            #pragma unroll
            for (int j = 1; j < 4; j++) if (hv[j] > best) { best = hv[j]; bj = j; }
            uint32_t bv = best; int bl = tid;
            #pragma unroll
            for (int off = 16; off > 0; off >>= 1) {
                uint32_t ov = __shfl_down_sync(0xffffffffu, bv, off);
                int      ol = __shfl_down_sync(0xffffffffu, bl, off);
                if (ov > bv) { bv = ov; bl = ol; }
            }
            bl = __shfl_sync(0xffffffffu, bl, 0);
            if (tid == bl) {
                int list = tid * 4 + bj;
                sel_ix[r] = (int)(hv[bj] & 0xFFFFu);
                h[bj]++;
                hv[bj] = (h[bj] < TOPT) ? cp_t[h[bj]][list] : 0u;
            }
            __syncwarp();
        }
    }
    __syncthreads();

    // exact f32 rescore: 16 threads per candidate, 32 candidates
    {
        int c = tid >> 4, part = tid & 15;
        int p = sel_ix[c];
        const float4* qv = (const float4*)(g_qvec + (size_t)q * D_ + part * 16);
        const float4* ev = (const float4*)(ent + ((size_t)sp * P_ + p) * D_ + part * 16);
        float accv = 0.f;
        #pragma unroll
        for (int i = 0; i < 4; i++) {
            float4 a = qv[i], e = ev[i];
            accv = fmaf(a.x, e.x, fmaf(a.y, e.y, fmaf(a.z, e.z, fmaf(a.w, e.w, accv))));
        }
        #pragma unroll
        for (int off = 8; off > 0; off >>= 1)
            accv += __shfl_down_sync(0xffffffffu, accv, off, 16);
        if (part == 0) fsc[c] = accv;
    }
    __syncthreads();

    // warp 0: exact top-11 of 32
    if (tid < 32) {
        float v = fsc[tid];
        int ix = sel_ix[tid];
        size_t ob = ((size_t)sp * Q_ + q) * NB;
        for (int r = 0; r < NB; r++) {
            float bv = v; int bl = tid;
            #pragma unroll
            for (int off = 16; off > 0; off >>= 1) {
                float ov = __shfl_down_sync(0xffffffffu, bv, off);
                int   ol = __shfl_down_sync(0xffffffffu, bl, off);
                if (ov > bv) { bv = ov; bl = ol; }
            }
            bl = __shfl_sync(0xffffffffu, bl, 0);
            float wv = __shfl_sync(0xffffffffu, v, bl);
            int   wi = __shfl_sync(0xffffffffu, ix, bl);
            if (tid == 0) { g_best_sc[ob + r] = wv; g_best_ix[ob + r] = wi; }
            if (tid == bl) v = NEG_INF;
            __syncwarp();
        }
    }
}

// ============================================================
// Kernel 3: per (s,b) merge 4 x 11 -> top-10; write output
// ============================================================
__global__ void final_kernel(float* __restrict__ out) {
    int q = blockIdx.x * blockDim.x + threadIdx.x;
    if (q >= Q_) return;
    float bs[KOUT]; int bg[KOUT];
    #pragma unroll
    for (int r = 0; r < KOUT; r++) { bs[r] = NEG_INF; bg[r] = -1; }
    for (int sp = 0; sp < S_; sp++) {
        size_t base = ((size_t)sp * Q_ + q) * NB;
        for (int r = 0; r < NB; r++) {
            float v = g_best_sc[base + r];
            if (v > bs[KOUT - 1]) {
                int gid = g_best_ix[base + r] * S_ + sp;
                float cv = v; int ci = gid;
                #pragma unroll
                for (int k = 0; k < KOUT; k++) {
                    if (cv > bs[k]) {
                        float t0 = bs[k]; int t1 = bg[k];
                        bs[k] = cv; bg[k] = ci; cv = t0; ci = t1;
                    }
                }
            }
        }
    }
    #pragma unroll
    for (int k = 0; k < KOUT; k++) {
        out[q * KOUT + k]             = (float)bg[k];
        out[Q_ * KOUT + q * KOUT + k] = bs[k];
    }
}

// ============================================================
extern "C" void kernel_launch(void* const* d_in, const int* in_sizes, int n_in,
                              void* d_out, int out_size) {
    const int*   relation = (const int*)d_in[0];
    const int*   head     = (const int*)d_in[1];
    const float* ent      = (const float*)d_in[2];
    const float* rel      = (const float*)d_in[3];
    float* out = (float*)d_out;

    cudaFuncSetAttribute(score_kernel, cudaFuncAttributeMaxDynamicSharedMemorySize, SM_TOTAL);

    conv_kernel<<<(int)(((size_t)S_ * P_ * D_ / 4) / 256), 256>>>(ent);
    qvec_kernel<<<Q_, D_>>>(relation, head, ent, rel);
    dim3 g1(NQT, NPT, S_);
    score_kernel<<<g1, 256, SM_TOTAL>>>();
    select_kernel<<<S_ * Q_, 512>>>(ent);
    final_kernel<<<4, 256>>>(out);
}

// round 15
// speedup vs baseline: 1.0695x; 1.0695x over previous
#include <cuda_runtime.h>
#include <cuda_fp16.h>
#include <cstdint>

#define S_   4
#define B_   256
#define Q_   1024
#define P_   32768
#define D_   256
#define NB   11
#define KOUT 10
#define NEG_INF (-1e30f)

#define PT    256           // p per score tile
#define NPT   128           // P_/PT
#define QT    128           // q per score tile
#define NQT   8             // Q_/QT
#define TOPT  8             // candidates kept per (q, ptile)
#define MSEL  32            // candidates rescored per (s',q)

// ---------------- static device scratch ----------------
__device__ float    g_qvec [Q_ * D_];
__device__ __half   g_qvech[Q_ * D_];
__device__ __half   g_enth [(size_t)S_ * P_ * D_];               // 64MB
__device__ uint32_t g_cand [(size_t)S_ * Q_ * NPT * TOPT];       // 16MB packed (mono16<<16)|p

__device__ __forceinline__ uint32_t smem_to_u32(const void* p) {
    uint32_t a;
    asm("{ .reg .u64 t; cvta.to.shared.u64 t, %1; cvt.u32.u64 %0, t; }" : "=r"(a) : "l"(p));
    return a;
}
// order-preserving f16 bits -> u16 code
__device__ __forceinline__ uint32_t mono16(uint32_t h) {
    uint32_t mask = (h & 0x8000u) ? 0xFFFFu : 0x8000u;
    return (h ^ mask) & 0xFFFFu;
}
// 16B-chunk XOR swizzle within a 512B row (32 chunks): conflict-free ldmatrix
__device__ __forceinline__ uint32_t swz(int row, int chunk) {
    int c = (chunk & ~7) | ((chunk ^ row) & 7);
    return (uint32_t)(row * 512 + c * 16);
}
__device__ __forceinline__ void cp_async16(uint32_t smem, const void* gmem) {
    asm volatile("cp.async.cg.shared.global [%0], [%1], 16;" :: "r"(smem), "l"(gmem));
}
__device__ __forceinline__ void cp_commit_wait() {
    asm volatile("cp.async.commit_group;");
    asm volatile("cp.async.wait_group 0;");
}
__device__ __forceinline__ void ldsm_x4(uint32_t* r, uint32_t addr) {
    asm volatile("ldmatrix.sync.aligned.m8n8.x4.shared.b16 {%0,%1,%2,%3}, [%4];"
                 : "=r"(r[0]), "=r"(r[1]), "=r"(r[2]), "=r"(r[3]) : "r"(addr));
}
__device__ __forceinline__ void ldsm_x2(uint32_t* r, uint32_t addr) {
    asm volatile("ldmatrix.sync.aligned.m8n8.x2.shared.b16 {%0,%1}, [%2];"
                 : "=r"(r[0]), "=r"(r[1]) : "r"(addr));
}
// f16 inputs, f16 accumulation
__device__ __forceinline__ void mma16816_f16(uint32_t* d, const uint32_t* a, const uint32_t* b) {
    asm volatile(
        "mma.sync.aligned.m16n8k16.row.col.f16.f16.f16.f16 "
        "{%0,%1}, {%2,%3,%4,%5}, {%6,%7}, {%0,%1};"
        : "+r"(d[0]), "+r"(d[1])
        : "r"(a[0]), "r"(a[1]), "r"(a[2]), "r"(a[3]), "r"(b[0]), "r"(b[1]));
}

// ============================================================
// Kernel 0a: ent f32 -> f16
// ============================================================
__global__ void conv_kernel(const float* __restrict__ ent) {
    size_t i = ((size_t)blockIdx.x * blockDim.x + threadIdx.x) * 4;
    float4 v = *(const float4*)(ent + i);
    *(__half2*)(g_enth + i)     = __floats2half2_rn(v.x, v.y);
    *(__half2*)(g_enth + i + 2) = __floats2half2_rn(v.z, v.w);
}

// ============================================================
// Kernel 0b: qvec f32 + f16
// ============================================================
__global__ void qvec_kernel(const int* __restrict__ relation,
                            const int* __restrict__ head,
                            const float* __restrict__ ent,
                            const float* __restrict__ rel) {
    int q = blockIdx.x, d = threadIdx.x;
    int s = q >> 8;
    int hd = head[q], rr = relation[q];
    float v = ent[((size_t)s * P_ + hd) * D_ + d] * rel[(size_t)rr * D_ + d];
    g_qvec[q * D_ + d]  = v;
    g_qvech[q * D_ + d] = __float2half_rn(v);
}

// ============================================================
// Kernel 1: HMMA f16 score + per-(q,ptile) packed top-8
// (proven R10 configuration: 16 warps, warp tile 64q x 32p)
// grid (8, 128, 4), block 512
// smem: A 64KB @0, B 128KB @65536
// epilogue overlay: sSh u32 [128][132] @0; scr [512][8] @98304
// ============================================================
#define SM_B_OFF   65536
#define SM_SH_STR  132
#define SM_SCR     98304
#define SM_TOTAL   196608

__global__ __launch_bounds__(512) void score_kernel() {
    extern __shared__ char sm[];
    const uint32_t sbase = smem_to_u32(sm);
    const int tid = threadIdx.x;
    const int wid = tid >> 5, lane = tid & 31;
    const int qtile = blockIdx.x, ptile = blockIdx.y, sp = blockIdx.z;

    // ---- stage A: 128 rows x 256 f16 ----
    {
        const __half* src = g_qvech + (size_t)qtile * QT * D_;
        #pragma unroll
        for (int it = 0; it < 8; it++) {
            int i = tid + it * 512;
            int row = i >> 5, ch = i & 31;
            cp_async16(sbase + swz(row, ch), src + (size_t)row * D_ + ch * 8);
        }
    }
    // ---- stage B: 256 rows x 256 f16 ----
    {
        const __half* src = g_enth + ((size_t)sp * P_ + (size_t)ptile * PT) * D_;
        #pragma unroll
        for (int it = 0; it < 16; it++) {
            int i = tid + it * 512;
            int row = i >> 5, ch = i & 31;
            cp_async16(sbase + SM_B_OFF + swz(row, ch), src + (size_t)row * D_ + ch * 8);
        }
    }
    cp_commit_wait();
    __syncthreads();

    // ---- MMA main loop: warp tile 64q x 32p, f16 accum ----
    const int wq = wid >> 3;
    const int wp = wid & 7;
    const int q0 = wq * 64, p0 = wp * 32;

    uint32_t d[4][4][2];
    #pragma unroll
    for (int mi = 0; mi < 4; mi++)
        #pragma unroll
        for (int ni = 0; ni < 4; ni++) { d[mi][ni][0] = 0u; d[mi][ni][1] = 0u; }

    const int arow = (lane & 15);
    const int asel = (lane >> 4);
    const int brow = (lane & 7);
    const int bsel = ((lane >> 3) & 1);

    #pragma unroll
    for (int ks = 0; ks < 16; ks++) {
        const int ch0 = ks * 2;
        uint32_t a[4][4], b[4][2];
        #pragma unroll
        for (int mi = 0; mi < 4; mi++)
            ldsm_x4(a[mi], sbase + swz(q0 + mi * 16 + arow, ch0 + asel));
        #pragma unroll
        for (int ni = 0; ni < 4; ni++)
            ldsm_x2(b[ni], sbase + SM_B_OFF + swz(p0 + ni * 8 + brow, ch0 + bsel));
        #pragma unroll
        for (int mi = 0; mi < 4; mi++)
            #pragma unroll
            for (int ni = 0; ni < 4; ni++)
                mma16816_f16(d[mi][ni], a[mi], b[ni]);
    }
    __syncthreads();   // staged tiles dead; epilogue overlays them

    // ---- dump raw f16x2 accum words -> sSh [128][132] (u32) ----
    uint32_t* sSh = (uint32_t*)sm;
    {
        int rr = lane >> 2, cc = 2 * (lane & 3);
        #pragma unroll
        for (int mi = 0; mi < 4; mi++)
            #pragma unroll
            for (int ni = 0; ni < 4; ni++) {
                int r  = q0 + mi * 16 + rr;
                int pr = (p0 + ni * 8 + cc) >> 1;     // pair index 0..127
                sSh[r * SM_SH_STR + pr]       = d[mi][ni][0];
                sSh[(r + 8) * SM_SH_STR + pr] = d[mi][ni][1];
            }
    }
    __syncthreads();

    // ---- per-thread packed top-8 over 64 p's (32 f16x2 words) ----
    uint32_t* scr = (uint32_t*)(sm + SM_SCR);   // [512][8]
    const int tq = tid >> 2, tsg = tid & 3;
    const int pg0 = ptile * PT;
    {
        uint32_t bs[TOPT];
        #pragma unroll
        for (int r = 0; r < TOPT; r++) bs[r] = 0u;
        #pragma unroll 8
        for (int i = 0; i < 32; i++) {
            int p2 = tsg + (i << 2);
            uint32_t u = sSh[tq * SM_SH_STR + p2];
            uint32_t v0 = (mono16(u & 0xFFFFu) << 16) | (uint32_t)(pg0 + 2 * p2);
            uint32_t v1 = (mono16(u >> 16)     << 16) | (uint32_t)(pg0 + 2 * p2 + 1);
            #pragma unroll
            for (int h = 0; h < 2; h++) {
                uint32_t v = h ? v1 : v0;
                if (v > bs[TOPT - 1]) {
                    uint32_t cv = v;
                    #pragma unroll
                    for (int r = 0; r < TOPT; r++) {
                        if (cv > bs[r]) { uint32_t t = bs[r]; bs[r] = cv; cv = t; }
                    }
                }
            }
        }
        #pragma unroll
        for (int r = 0; r < TOPT; r++)
            scr[(tq * 4 + tsg) * TOPT + r] = bs[r];
    }
    __syncthreads();

    // ---- leader: merge 4 sorted packed top-8 lists -> top-8, write ----
    if (tsg == 0) {
        int q = qtile * QT + tq;
        size_t ob = (((size_t)sp * Q_ + q) * NPT + ptile) * TOPT;
        int h0 = 0, h1 = 0, h2 = 0, h3 = 0;
        const uint32_t* L = scr + (size_t)tq * 4 * TOPT;
        #pragma unroll
        for (int r = 0; r < TOPT; r++) {
            uint32_t best = 0u; int bj = 0;
            #define TRYM(j, h) { uint32_t v = ((h) < TOPT) ? L[(j) * TOPT + (h)] : 0u; \
                                 if (v > best) { best = v; bj = (j); } }
            TRYM(0, h0) TRYM(1, h1) TRYM(2, h2) TRYM(3, h3)
            #undef TRYM
            g_cand[ob + r] = best;
            if      (bj == 0) h0++;
            else if (bj == 1) h1++;
            else if (bj == 2) h2++;
            else              h3++;
        }
    }
}

// ============================================================
// Kernel 2 (v2): one block per q; all 4 sp fused.
// 4 parallel tournaments (warp per sp) -> 4 x top-32 approx,
// 128-candidate exact f32 rescore, 4 parallel top-11,
// 4-way sorted merge -> top-10, write output directly.
// grid 1024, block 512
// ============================================================
__global__ __launch_bounds__(512) void select_kernel(const float* __restrict__ ent,
                                                     float* __restrict__ out) {
    __shared__ uint32_t cp_t[S_][TOPT][NPT];   // [sp][rank][list]  16 KB
    __shared__ float    sqv[D_];               // qvec row, 1 KB
    __shared__ int      sel_ix[S_ * MSEL];     // 128 candidates
    __shared__ float    fsc[S_ * MSEL];
    __shared__ float    bsc[S_][NB];
    __shared__ int      bix[S_][NB];

    const int tid = threadIdx.x;
    const int q = blockIdx.x;
    const int wid = tid >> 5, lane = tid & 31;

    // ---- load candidates (all 4 sp) + qvec row ----
    for (int e = tid; e < S_ * NPT * TOPT; e += 512) {
        int sp = e >> 10, r = e & 1023;
        cp_t[sp][r & 7][r >> 3] = g_cand[((size_t)sp * Q_ + q) * (NPT * TOPT) + r];
    }
    for (int i = tid; i < D_; i += 512)
        sqv[i] = g_qvec[q * D_ + i];
    __syncthreads();

    // ---- warps 0-3: parallel tournaments (one per sp) ----
    if (wid < S_) {
        const int sp = wid;
        int      h[4];
        uint32_t hv[4];
        #pragma unroll
        for (int j = 0; j < 4; j++) { h[j] = 0; hv[j] = cp_t[sp][0][lane * 4 + j]; }
        for (int r = 0; r < MSEL; r++) {
            uint32_t best = hv[0]; int bj = 0;
            #pragma unroll
            for (int j = 1; j < 4; j++) if (hv[j] > best) { best = hv[j]; bj = j; }
            uint32_t bv = best; int bl = lane;
            #pragma unroll
            for (int off = 16; off > 0; off >>= 1) {
                uint32_t ov = __shfl_down_sync(0xffffffffu, bv, off);
                int      ol = __shfl_down_sync(0xffffffffu, bl, off);
                if (ov > bv) { bv = ov; bl = ol; }
            }
            bl = __shfl_sync(0xffffffffu, bl, 0);
            if (lane == bl) {
                int list = lane * 4 + bj;
                sel_ix[sp * MSEL + r] = (int)(hv[bj] & 0xFFFFu);
                h[bj]++;
                hv[bj] = (h[bj] < TOPT) ? cp_t[sp][h[bj]][list] : 0u;
            }
            __syncwarp();
        }
    }
    __syncthreads();

    // ---- exact f32 rescore: 4 threads per candidate, 128 candidates ----
    {
        int c = tid >> 2, part = tid & 3;     // c: 0..127; sp = c >> 5
        int sp = c >> 5;
        int p = sel_ix[c];
        const float4* qv = (const float4*)sqv + part * 16;
        const float4* ev = (const float4*)(ent + ((size_t)sp * P_ + p) * D_) + part * 16;
        float accv = 0.f;
        #pragma unroll
        for (int i = 0; i < 16; i++) {
            float4 a = qv[i], e = ev[i];
            accv = fmaf(a.x, e.x, fmaf(a.y, e.y, fmaf(a.z, e.z, fmaf(a.w, e.w, accv))));
        }
        accv += __shfl_down_sync(0xffffffffu, accv, 2, 4);
        accv += __shfl_down_sync(0xffffffffu, accv, 1, 4);
        if (part == 0) fsc[c] = accv;
    }
    __syncthreads();

    // ---- warps 0-3: parallel exact top-11 of 32 (one per sp) ----
    if (wid < S_) {
        const int sp = wid;
        float v = fsc[sp * MSEL + lane];
        int  ix = sel_ix[sp * MSEL + lane];
        for (int r = 0; r < NB; r++) {
            float bv = v; int bl = lane;
            #pragma unroll
            for (int off = 16; off > 0; off >>= 1) {
                float ov = __shfl_down_sync(0xffffffffu, bv, off);
                int   ol = __shfl_down_sync(0xffffffffu, bl, off);
                if (ov > bv) { bv = ov; bl = ol; }
            }
            bl = __shfl_sync(0xffffffffu, bl, 0);
            float wv = __shfl_sync(0xffffffffu, v, bl);
            int   wi = __shfl_sync(0xffffffffu, ix, bl);
            if (lane == 0) { bsc[sp][r] = wv; bix[sp][r] = wi; }
            if (lane == bl) v = NEG_INF;
            __syncwarp();
        }
    }
    __syncthreads();

    // ---- thread 0: 4-way sorted merge -> top-10, write output ----
    // tie rule: scan sp ascending with strict > (matches stable top_k)
    if (tid == 0) {
        int h0 = 0, h1 = 0, h2 = 0, h3 = 0;
        #pragma unroll
        for (int k = 0; k < KOUT; k++) {
            float best = NEG_INF; int bsp = 0;
            #define TRYS(spv, h) { float v = ((h) < NB) ? bsc[spv][h] : NEG_INF; \
                                   if (v > best) { best = v; bsp = (spv); } }
            TRYS(0, h0) TRYS(1, h1) TRYS(2, h2) TRYS(3, h3)
            #undef TRYS
            int hh = (bsp == 0) ? h0 : (bsp == 1) ? h1 : (bsp == 2) ? h2 : h3;
            int gid = bix[bsp][hh] * S_ + bsp;
            out[q * KOUT + k]             = (float)gid;
            out[Q_ * KOUT + q * KOUT + k] = best;
            if      (bsp == 0) h0++;
            else if (bsp == 1) h1++;
            else if (bsp == 2) h2++;
            else               h3++;
        }
    }
}

// ============================================================
extern "C" void kernel_launch(void* const* d_in, const int* in_sizes, int n_in,
                              void* d_out, int out_size) {
    const int*   relation = (const int*)d_in[0];
    const int*   head     = (const int*)d_in[1];
    const float* ent      = (const float*)d_in[2];
    const float* rel      = (const float*)d_in[3];
    float* out = (float*)d_out;

    cudaFuncSetAttribute(score_kernel, cudaFuncAttributeMaxDynamicSharedMemorySize, SM_TOTAL);

    conv_kernel<<<(int)(((size_t)S_ * P_ * D_ / 4) / 256), 256>>>(ent);
    qvec_kernel<<<Q_, D_>>>(relation, head, ent, rel);
    dim3 g1(NQT, NPT, S_);
    score_kernel<<<g1, 512, SM_TOTAL>>>();
    select_kernel<<<Q_, 512>>>(ent, out);
}

// round 16
// speedup vs baseline: 1.1099x; 1.0378x over previous
#include <cuda_runtime.h>
#include <cuda_fp16.h>
#include <cstdint>

#define S_   4
#define B_   256
#define Q_   1024
#define P_   32768
#define D_   256
#define NB   11
#define KOUT 10
#define NEG_INF (-1e30f)

#define PT    256           // p per score tile
#define NPT   128           // P_/PT
#define QT    128           // q per score tile
#define NQT   8             // Q_/QT
#define QPC   4             // qtiles per CTA
#define TOPT  8             // candidates kept per (q, ptile)
#define MSEL  32            // candidates rescored per (s',q)

// ---------------- static device scratch ----------------
__device__ float    g_qvec [Q_ * D_];
__device__ __half   g_qvech[Q_ * D_];
__device__ __half   g_enth [(size_t)S_ * P_ * D_];               // 64MB
__device__ uint32_t g_cand [(size_t)S_ * Q_ * NPT * TOPT];       // 16MB packed (mono16<<16)|p

__device__ __forceinline__ uint32_t smem_to_u32(const void* p) {
    uint32_t a;
    asm("{ .reg .u64 t; cvta.to.shared.u64 t, %1; cvt.u32.u64 %0, t; }" : "=r"(a) : "l"(p));
    return a;
}
// order-preserving f16 bits -> u16 code
__device__ __forceinline__ uint32_t mono16(uint32_t h) {
    uint32_t mask = (h & 0x8000u) ? 0xFFFFu : 0x8000u;
    return (h ^ mask) & 0xFFFFu;
}
// 16B-chunk XOR swizzle within a 512B row (32 chunks): conflict-free ldmatrix
__device__ __forceinline__ uint32_t swz(int row, int chunk) {
    int c = (chunk & ~7) | ((chunk ^ row) & 7);
    return (uint32_t)(row * 512 + c * 16);
}
__device__ __forceinline__ void cp_async16(uint32_t smem, const void* gmem) {
    asm volatile("cp.async.cg.shared.global [%0], [%1], 16;" :: "r"(smem), "l"(gmem));
}
__device__ __forceinline__ void cp_commit_wait() {
    asm volatile("cp.async.commit_group;");
    asm volatile("cp.async.wait_group 0;");
}
__device__ __forceinline__ void ldsm_x4(uint32_t* r, uint32_t addr) {
    asm volatile("ldmatrix.sync.aligned.m8n8.x4.shared.b16 {%0,%1,%2,%3}, [%4];"
                 : "=r"(r[0]), "=r"(r[1]), "=r"(r[2]), "=r"(r[3]) : "r"(addr));
}
__device__ __forceinline__ void ldsm_x2(uint32_t* r, uint32_t addr) {
    asm volatile("ldmatrix.sync.aligned.m8n8.x2.shared.b16 {%0,%1}, [%2];"
                 : "=r"(r[0]), "=r"(r[1]) : "r"(addr));
}
// f16 inputs, f16 accumulation
__device__ __forceinline__ void mma16816_f16(uint32_t* d, const uint32_t* a, const uint32_t* b) {
    asm volatile(
        "mma.sync.aligned.m16n8k16.row.col.f16.f16.f16.f16 "
        "{%0,%1}, {%2,%3,%4,%5}, {%6,%7}, {%0,%1};"
        : "+r"(d[0]), "+r"(d[1])
        : "r"(a[0]), "r"(a[1]), "r"(a[2]), "r"(a[3]), "r"(b[0]), "r"(b[1]));
}

// ============================================================
// Kernel 0a: ent f32 -> f16
// ============================================================
__global__ void conv_kernel(const float* __restrict__ ent) {
    size_t i = ((size_t)blockIdx.x * blockDim.x + threadIdx.x) * 4;
    float4 v = *(const float4*)(ent + i);
    *(__half2*)(g_enth + i)     = __floats2half2_rn(v.x, v.y);
    *(__half2*)(g_enth + i + 2) = __floats2half2_rn(v.z, v.w);
}

// ============================================================
// Kernel 0b: qvec f32 + f16
// ============================================================
__global__ void qvec_kernel(const int* __restrict__ relation,
                            const int* __restrict__ head,
                            const float* __restrict__ ent,
                            const float* __restrict__ rel) {
    int q = blockIdx.x, d = threadIdx.x;
    int s = q >> 8;
    int hd = head[q], rr = relation[q];
    float v = ent[((size_t)s * P_ + hd) * D_ + d] * rel[(size_t)rr * D_ + d];
    g_qvec[q * D_ + d]  = v;
    g_qvech[q * D_ + d] = __float2half_rn(v);
}

// ============================================================
// Kernel 1: HMMA f16 score, persistent over 4 qtiles per CTA
// grid (2, 128, 4), block 512 (16 warps; warp tile 64q x 32p)
// smem: A 64KB @0 (restaged per qtile), B 128KB @65536 (once)
// per-qtile epilogue overlays dead A region:
//   sSh u32 [128][128] with col swizzle (pr + 4r) & 127
// leader merge: 4-lane shfl butterfly (no smem scratch)
// ============================================================
#define SM_B_OFF   65536
#define SM_TOTAL   196608

__global__ __launch_bounds__(512) void score_kernel() {
    extern __shared__ char sm[];
    const uint32_t sbase = smem_to_u32(sm);
    const int tid = threadIdx.x;
    const int wid = tid >> 5, lane = tid & 31;
    const int qhalf = blockIdx.x, ptile = blockIdx.y, sp = blockIdx.z;

    // ---- stage B once: 256 rows x 256 f16 ----
    {
        const __half* src = g_enth + ((size_t)sp * P_ + (size_t)ptile * PT) * D_;
        #pragma unroll
        for (int it = 0; it < 16; it++) {
            int i = tid + it * 512;
            int row = i >> 5, ch = i & 31;
            cp_async16(sbase + SM_B_OFF + swz(row, ch), src + (size_t)row * D_ + ch * 8);
        }
    }
    // ---- stage A for first qtile ----
    {
        const __half* src = g_qvech + (size_t)(qhalf * QPC) * QT * D_;
        #pragma unroll
        for (int it = 0; it < 8; it++) {
            int i = tid + it * 512;
            int row = i >> 5, ch = i & 31;
            cp_async16(sbase + swz(row, ch), src + (size_t)row * D_ + ch * 8);
        }
    }
    cp_commit_wait();
    __syncthreads();

    const int wq = wid >> 3;
    const int wp = wid & 7;
    const int q0 = wq * 64, p0 = wp * 32;
    const int arow = (lane & 15);
    const int asel = (lane >> 4);
    const int brow = (lane & 7);
    const int bsel = ((lane >> 3) & 1);
    const int tq = tid >> 2, tsg = tid & 3;
    const int pg0 = ptile * PT;

    for (int qt = 0; qt < QPC; qt++) {
        // ---- MMA: warp tile 64q x 32p, f16 accum ----
        uint32_t d[4][4][2];
        #pragma unroll
        for (int mi = 0; mi < 4; mi++)
            #pragma unroll
            for (int ni = 0; ni < 4; ni++) { d[mi][ni][0] = 0u; d[mi][ni][1] = 0u; }

        #pragma unroll
        for (int ks = 0; ks < 16; ks++) {
            const int ch0 = ks * 2;
            uint32_t a[4][4], b[4][2];
            #pragma unroll
            for (int mi = 0; mi < 4; mi++)
                ldsm_x4(a[mi], sbase + swz(q0 + mi * 16 + arow, ch0 + asel));
            #pragma unroll
            for (int ni = 0; ni < 4; ni++)
                ldsm_x2(b[ni], sbase + SM_B_OFF + swz(p0 + ni * 8 + brow, ch0 + bsel));
            #pragma unroll
            for (int mi = 0; mi < 4; mi++)
                #pragma unroll
                for (int ni = 0; ni < 4; ni++)
                    mma16816_f16(d[mi][ni], a[mi], b[ni]);
        }
        __syncthreads();   // A reads done; overlay with score dump

        // ---- dump raw f16x2 accum -> sSh[128][128], col (pr+4r)&127 ----
        uint32_t* sSh = (uint32_t*)sm;
        {
            int rr = lane >> 2, cl = lane & 3;
            #pragma unroll
            for (int mi = 0; mi < 4; mi++)
                #pragma unroll
                for (int ni = 0; ni < 4; ni++) {
                    int pr = (p0 >> 1) + ni * 4 + cl;
                    int r0 = q0 + mi * 16 + rr;
                    int r1 = r0 + 8;
                    sSh[r0 * 128 + ((pr + 4 * r0) & 127)] = d[mi][ni][0];
                    sSh[r1 * 128 + ((pr + 4 * r1) & 127)] = d[mi][ni][1];
                }
        }
        __syncthreads();

        // ---- per-thread packed top-8 over 64 p's (32 f16x2 words) ----
        uint32_t bs[TOPT];
        #pragma unroll
        for (int r = 0; r < TOPT; r++) bs[r] = 0u;
        #pragma unroll 8
        for (int i = 0; i < 32; i++) {
            int p2 = tsg + (i << 2);
            uint32_t u = sSh[tq * 128 + ((p2 + 4 * tq) & 127)];
            uint32_t v0 = (mono16(u & 0xFFFFu) << 16) | (uint32_t)(pg0 + 2 * p2);
            uint32_t v1 = (mono16(u >> 16)     << 16) | (uint32_t)(pg0 + 2 * p2 + 1);
            #pragma unroll
            for (int h = 0; h < 2; h++) {
                uint32_t v = h ? v1 : v0;
                if (v > bs[TOPT - 1]) {
                    uint32_t cv = v;
                    #pragma unroll
                    for (int r = 0; r < TOPT; r++) {
                        if (cv > bs[r]) { uint32_t t = bs[r]; bs[r] = cv; cv = t; }
                    }
                }
            }
        }

        // ---- 4-lane shfl butterfly merge (ties impossible: distinct p) ----
        uint32_t outv[TOPT];
        #pragma unroll
        for (int r = 0; r < TOPT; r++) {
            uint32_t m = bs[0]; int ml = lane;
            {
                uint32_t ov = __shfl_xor_sync(0xffffffffu, m, 1);
                int      ol = __shfl_xor_sync(0xffffffffu, ml, 1);
                if (ov > m) { m = ov; ml = ol; }
            }
            {
                uint32_t ov = __shfl_xor_sync(0xffffffffu, m, 2);
                int      ol = __shfl_xor_sync(0xffffffffu, ml, 2);
                if (ov > m) { m = ov; ml = ol; }
            }
            if (lane == ml) {
                #pragma unroll
                for (int j = 0; j < TOPT - 1; j++) bs[j] = bs[j + 1];
                bs[TOPT - 1] = 0u;
            }
            outv[r] = m;
        }
        if (tsg == 0) {
            int q = (qhalf * QPC + qt) * QT + tq;
            size_t ob = (((size_t)sp * Q_ + q) * NPT + ptile) * TOPT;
            #pragma unroll
            for (int r = 0; r < TOPT; r++) g_cand[ob + r] = outv[r];
        }
        __syncthreads();   // all sSh reads done before restaging A

        // ---- restage A for next qtile ----
        if (qt < QPC - 1) {
            const __half* src = g_qvech + (size_t)(qhalf * QPC + qt + 1) * QT * D_;
            #pragma unroll
            for (int it = 0; it < 8; it++) {
                int i = tid + it * 512;
                int row = i >> 5, ch = i & 31;
                cp_async16(sbase + swz(row, ch), src + (size_t)row * D_ + ch * 8);
            }
            cp_commit_wait();
            __syncthreads();
        }
    }
}

// ============================================================
// Kernel 2: one block per q; all 4 sp fused (proven R15 config).
// 4 parallel tournaments -> 4 x top-32 approx, 128-candidate
// exact f32 rescore, 4 parallel top-11, merge -> top-10, write.
// grid 1024, block 512
// ============================================================
__global__ __launch_bounds__(512) void select_kernel(const float* __restrict__ ent,
                                                     float* __restrict__ out) {
    __shared__ uint32_t cp_t[S_][TOPT][NPT];   // [sp][rank][list]  16 KB
    __shared__ float    sqv[D_];               // qvec row, 1 KB
    __shared__ int      sel_ix[S_ * MSEL];     // 128 candidates
    __shared__ float    fsc[S_ * MSEL];
    __shared__ float    bsc[S_][NB];
    __shared__ int      bix[S_][NB];

    const int tid = threadIdx.x;
    const int q = blockIdx.x;
    const int wid = tid >> 5, lane = tid & 31;

    // ---- load candidates (all 4 sp) + qvec row ----
    for (int e = tid; e < S_ * NPT * TOPT; e += 512) {
        int sp = e >> 10, r = e & 1023;
        cp_t[sp][r & 7][r >> 3] = g_cand[((size_t)sp * Q_ + q) * (NPT * TOPT) + r];
    }
    for (int i = tid; i < D_; i += 512)
        sqv[i] = g_qvec[q * D_ + i];
    __syncthreads();

    // ---- warps 0-3: parallel tournaments (one per sp) ----
    if (wid < S_) {
        const int sp = wid;
        int      h[4];
        uint32_t hv[4];
        #pragma unroll
        for (int j = 0; j < 4; j++) { h[j] = 0; hv[j] = cp_t[sp][0][lane * 4 + j]; }
        for (int r = 0; r < MSEL; r++) {
            uint32_t best = hv[0]; int bj = 0;
            #pragma unroll
            for (int j = 1; j < 4; j++) if (hv[j] > best) { best = hv[j]; bj = j; }
            uint32_t bv = best; int bl = lane;
            #pragma unroll
            for (int off = 16; off > 0; off >>= 1) {
                uint32_t ov = __shfl_down_sync(0xffffffffu, bv, off);
                int      ol = __shfl_down_sync(0xffffffffu, bl, off);
                if (ov > bv) { bv = ov; bl = ol; }
            }
            bl = __shfl_sync(0xffffffffu, bl, 0);
            if (lane == bl) {
                int list = lane * 4 + bj;
                sel_ix[sp * MSEL + r] = (int)(hv[bj] & 0xFFFFu);
                h[bj]++;
                hv[bj] = (h[bj] < TOPT) ? cp_t[sp][h[bj]][list] : 0u;
            }
            __syncwarp();
        }
    }
    __syncthreads();

    // ---- exact f32 rescore: 4 threads per candidate, 128 candidates ----
    {
        int c = tid >> 2, part = tid & 3;
        int sp = c >> 5;
        int p = sel_ix[c];
        const float4* qv = (const float4*)sqv + part * 16;
        const float4* ev = (const float4*)(ent + ((size_t)sp * P_ + p) * D_) + part * 16;
        float accv = 0.f;
        #pragma unroll
        for (int i = 0; i < 16; i++) {
            float4 a = qv[i], e = ev[i];
            accv = fmaf(a.x, e.x, fmaf(a.y, e.y, fmaf(a.z, e.z, fmaf(a.w, e.w, accv))));
        }
        accv += __shfl_down_sync(0xffffffffu, accv, 2, 4);
        accv += __shfl_down_sync(0xffffffffu, accv, 1, 4);
        if (part == 0) fsc[c] = accv;
    }
    __syncthreads();

    // ---- warps 0-3: parallel exact top-11 of 32 (one per sp) ----
    if (wid < S_) {
        const int sp = wid;
        float v = fsc[sp * MSEL + lane];
        int  ix = sel_ix[sp * MSEL + lane];
        for (int r = 0; r < NB; r++) {
            float bv = v; int bl = lane;
            #pragma unroll
            for (int off = 16; off > 0; off >>= 1) {
                float ov = __shfl_down_sync(0xffffffffu, bv, off);
                int   ol = __shfl_down_sync(0xffffffffu, bl, off);
                if (ov > bv) { bv = ov; bl = ol; }
            }
            bl = __shfl_sync(0xffffffffu, bl, 0);
            float wv = __shfl_sync(0xffffffffu, v, bl);
            int   wi = __shfl_sync(0xffffffffu, ix, bl);
            if (lane == 0) { bsc[sp][r] = wv; bix[sp][r] = wi; }
            if (lane == bl) v = NEG_INF;
            __syncwarp();
        }
    }
    __syncthreads();

    // ---- thread 0: 4-way sorted merge -> top-10, write output ----
    if (tid == 0) {
        int h0 = 0, h1 = 0, h2 = 0, h3 = 0;
        #pragma unroll
        for (int k = 0; k < KOUT; k++) {
            float best = NEG_INF; int bsp = 0;
            #define TRYS(spv, h) { float v = ((h) < NB) ? bsc[spv][h] : NEG_INF; \
                                   if (v > best) { best = v; bsp = (spv); } }
            TRYS(0, h0) TRYS(1, h1) TRYS(2, h2) TRYS(3, h3)
            #undef TRYS
            int hh = (bsp == 0) ? h0 : (bsp == 1) ? h1 : (bsp == 2) ? h2 : h3;
            int gid = bix[bsp][hh] * S_ + bsp;
            out[q * KOUT + k]             = (float)gid;
            out[Q_ * KOUT + q * KOUT + k] = best;
            if      (bsp == 0) h0++;
            else if (bsp == 1) h1++;
            else if (bsp == 2) h2++;
            else               h3++;
        }
    }
}

// ============================================================
extern "C" void kernel_launch(void* const* d_in, const int* in_sizes, int n_in,
                              void* d_out, int out_size) {
    const int*   relation = (const int*)d_in[0];
    const int*   head     = (const int*)d_in[1];
    const float* ent      = (const float*)d_in[2];
    const float* rel      = (const float*)d_in[3];
    float* out = (float*)d_out;

    cudaFuncSetAttribute(score_kernel, cudaFuncAttributeMaxDynamicSharedMemorySize, SM_TOTAL);

    conv_kernel<<<(int)(((size_t)S_ * P_ * D_ / 4) / 256), 256>>>(ent);
    qvec_kernel<<<Q_, D_>>>(relation, head, ent, rel);
    dim3 g1(2, NPT, S_);
    score_kernel<<<g1, 512, SM_TOTAL>>>();
    select_kernel<<<Q_, 512>>>(ent, out);
}

// round 17
// speedup vs baseline: 1.1488x; 1.0351x over previous
#include <cuda_runtime.h>
#include <cuda_fp16.h>
#include <cstdint>

#define S_   4
#define B_   256
#define Q_   1024
#define P_   32768
#define D_   256
#define NB   11
#define KOUT 10
#define NEG_INF (-1e30f)

#define PT    256           // p per score tile
#define NPT   128           // P_/PT
#define QT    128           // q per score tile
#define NQT   8             // Q_/QT
#define QPC   4             // qtiles per CTA
#define TOPT  8             // candidates kept per (q, ptile)
#define MSEL  32            // candidates rescored per (s',q)

// ---------------- static device scratch ----------------
__device__ float    g_qvec [Q_ * D_];
__device__ __half   g_qvech[Q_ * D_];
__device__ uint32_t g_cand [(size_t)S_ * Q_ * NPT * TOPT];       // 16MB packed (mono16<<16)|p

__device__ __forceinline__ uint32_t smem_to_u32(const void* p) {
    uint32_t a;
    asm("{ .reg .u64 t; cvta.to.shared.u64 t, %1; cvt.u32.u64 %0, t; }" : "=r"(a) : "l"(p));
    return a;
}
// order-preserving f16 bits -> u16 code
__device__ __forceinline__ uint32_t mono16(uint32_t h) {
    uint32_t mask = (h & 0x8000u) ? 0xFFFFu : 0x8000u;
    return (h ^ mask) & 0xFFFFu;
}
// 16B-chunk XOR swizzle within a 512B row (32 chunks): conflict-free ldmatrix
__device__ __forceinline__ uint32_t swz(int row, int chunk) {
    int c = (chunk & ~7) | ((chunk ^ row) & 7);
    return (uint32_t)(row * 512 + c * 16);
}
__device__ __forceinline__ void cp_async16(uint32_t smem, const void* gmem) {
    asm volatile("cp.async.cg.shared.global [%0], [%1], 16;" :: "r"(smem), "l"(gmem));
}
__device__ __forceinline__ void cp_commit_wait() {
    asm volatile("cp.async.commit_group;");
    asm volatile("cp.async.wait_group 0;");
}
__device__ __forceinline__ void ldsm_x4(uint32_t* r, uint32_t addr) {
    asm volatile("ldmatrix.sync.aligned.m8n8.x4.shared.b16 {%0,%1,%2,%3}, [%4];"
                 : "=r"(r[0]), "=r"(r[1]), "=r"(r[2]), "=r"(r[3]) : "r"(addr));
}
__device__ __forceinline__ void ldsm_x2(uint32_t* r, uint32_t addr) {
    asm volatile("ldmatrix.sync.aligned.m8n8.x2.shared.b16 {%0,%1}, [%2];"
                 : "=r"(r[0]), "=r"(r[1]) : "r"(addr));
}
// f16 inputs, f16 accumulation
__device__ __forceinline__ void mma16816_f16(uint32_t* d, const uint32_t* a, const uint32_t* b) {
    asm volatile(
        "mma.sync.aligned.m16n8k16.row.col.f16.f16.f16.f16 "
        "{%0,%1}, {%2,%3,%4,%5}, {%6,%7}, {%0,%1};"
        : "+r"(d[0]), "+r"(d[1])
        : "r"(a[0]), "r"(a[1]), "r"(a[2]), "r"(a[3]), "r"(b[0]), "r"(b[1]));
}
__device__ __forceinline__ void sts64(uint32_t addr, uint32_t lo, uint32_t hi) {
    asm volatile("st.shared.v2.u32 [%0], {%1, %2};" :: "r"(addr), "r"(lo), "r"(hi));
}

// ============================================================
// Kernel 0: qvec f32 + f16
// ============================================================
__global__ void qvec_kernel(const int* __restrict__ relation,
                            const int* __restrict__ head,
                            const float* __restrict__ ent,
                            const float* __restrict__ rel) {
    int q = blockIdx.x, d = threadIdx.x;
    int s = q >> 8;
    int hd = head[q], rr = relation[q];
    float v = ent[((size_t)s * P_ + hd) * D_ + d] * rel[(size_t)rr * D_ + d];
    g_qvec[q * D_ + d]  = v;
    g_qvech[q * D_ + d] = __float2half_rn(v);
}

// ============================================================
// Kernel 1: HMMA f16 score, persistent over 4 qtiles per CTA.
// B staged ONCE per CTA directly from f32 ent (LDG+cvt+STS,
// hidden under A's cp.async + MMA) — conv kernel eliminated.
// grid (2, 128, 4), block 512 (16 warps; warp tile 64q x 32p)
// smem: A 64KB @0 (restaged per qtile via cp.async), B 128KB @65536
// per-qtile epilogue overlays dead A region:
//   sSh u32 [128][128] with col swizzle (pr + 4r) & 127
// ============================================================
#define SM_B_OFF   65536
#define SM_TOTAL   196608

__global__ __launch_bounds__(512) void score_kernel(const float* __restrict__ ent) {
    extern __shared__ char sm[];
    const uint32_t sbase = smem_to_u32(sm);
    const int tid = threadIdx.x;
    const int wid = tid >> 5, lane = tid & 31;
    const int qhalf = blockIdx.x, ptile = blockIdx.y, sp = blockIdx.z;

    // ---- stage A for first qtile (async; overlaps B convert) ----
    {
        const __half* src = g_qvech + (size_t)(qhalf * QPC) * QT * D_;
        #pragma unroll
        for (int it = 0; it < 8; it++) {
            int i = tid + it * 512;
            int row = i >> 5, ch = i & 31;
            cp_async16(sbase + swz(row, ch), src + (size_t)row * D_ + ch * 8);
        }
    }
    asm volatile("cp.async.commit_group;");
    // ---- stage B once: 256 rows x 256, f32 -> f16 inline ----
    {
        const float* src = ent + ((size_t)sp * P_ + (size_t)ptile * PT) * D_;
        #pragma unroll
        for (int it = 0; it < 32; it++) {
            int i = tid + it * 512;                 // 16384 float4s
            int row = i >> 6, f4 = i & 63;
            float4 v = *(const float4*)(src + (size_t)row * D_ + f4 * 4);
            __half2 h0 = __floats2half2_rn(v.x, v.y);
            __half2 h1 = __floats2half2_rn(v.z, v.w);
            uint32_t addr = sbase + SM_B_OFF + swz(row, f4 >> 1) + (f4 & 1) * 8;
            sts64(addr, *(uint32_t*)&h0, *(uint32_t*)&h1);
        }
    }
    asm volatile("cp.async.wait_group 0;");
    __syncthreads();

    const int wq = wid >> 3;
    const int wp = wid & 7;
    const int q0 = wq * 64, p0 = wp * 32;
    const int arow = (lane & 15);
    const int asel = (lane >> 4);
    const int brow = (lane & 7);
    const int bsel = ((lane >> 3) & 1);
    const int tq = tid >> 2, tsg = tid & 3;
    const int pg0 = ptile * PT;

    for (int qt = 0; qt < QPC; qt++) {
        // ---- MMA: warp tile 64q x 32p, f16 accum ----
        uint32_t d[4][4][2];
        #pragma unroll
        for (int mi = 0; mi < 4; mi++)
            #pragma unroll
            for (int ni = 0; ni < 4; ni++) { d[mi][ni][0] = 0u; d[mi][ni][1] = 0u; }

        #pragma unroll
        for (int ks = 0; ks < 16; ks++) {
            const int ch0 = ks * 2;
            uint32_t a[4][4], b[4][2];
            #pragma unroll
            for (int mi = 0; mi < 4; mi++)
                ldsm_x4(a[mi], sbase + swz(q0 + mi * 16 + arow, ch0 + asel));
            #pragma unroll
            for (int ni = 0; ni < 4; ni++)
                ldsm_x2(b[ni], sbase + SM_B_OFF + swz(p0 + ni * 8 + brow, ch0 + bsel));
            #pragma unroll
            for (int mi = 0; mi < 4; mi++)
                #pragma unroll
                for (int ni = 0; ni < 4; ni++)
                    mma16816_f16(d[mi][ni], a[mi], b[ni]);
        }
        __syncthreads();   // A reads done; overlay with score dump

        // ---- dump raw f16x2 accum -> sSh[128][128], col (pr+4r)&127 ----
        uint32_t* sSh = (uint32_t*)sm;
        {
            int rr = lane >> 2, cl = lane & 3;
            #pragma unroll
            for (int mi = 0; mi < 4; mi++)
                #pragma unroll
                for (int ni = 0; ni < 4; ni++) {
                    int pr = (p0 >> 1) + ni * 4 + cl;
                    int r0 = q0 + mi * 16 + rr;
                    int r1 = r0 + 8;
                    sSh[r0 * 128 + ((pr + 4 * r0) & 127)] = d[mi][ni][0];
                    sSh[r1 * 128 + ((pr + 4 * r1) & 127)] = d[mi][ni][1];
                }
        }
        __syncthreads();

        // ---- per-thread packed top-8 over 64 p's (32 f16x2 words) ----
        uint32_t bs[TOPT];
        #pragma unroll
        for (int r = 0; r < TOPT; r++) bs[r] = 0u;
        #pragma unroll 8
        for (int i = 0; i < 32; i++) {
            int p2 = tsg + (i << 2);
            uint32_t u = sSh[tq * 128 + ((p2 + 4 * tq) & 127)];
            uint32_t v0 = (mono16(u & 0xFFFFu) << 16) | (uint32_t)(pg0 + 2 * p2);
            uint32_t v1 = (mono16(u >> 16)     << 16) | (uint32_t)(pg0 + 2 * p2 + 1);
            #pragma unroll
            for (int h = 0; h < 2; h++) {
                uint32_t v = h ? v1 : v0;
                if (v > bs[TOPT - 1]) {
                    uint32_t cv = v;
                    #pragma unroll
                    for (int r = 0; r < TOPT; r++) {
                        if (cv > bs[r]) { uint32_t t = bs[r]; bs[r] = cv; cv = t; }
                    }
                }
            }
        }

        // ---- 4-lane shfl butterfly merge (ties impossible: distinct p) ----
        uint32_t outv[TOPT];
        #pragma unroll
        for (int r = 0; r < TOPT; r++) {
            uint32_t m = bs[0]; int ml = lane;
            {
                uint32_t ov = __shfl_xor_sync(0xffffffffu, m, 1);
                int      ol = __shfl_xor_sync(0xffffffffu, ml, 1);
                if (ov > m) { m = ov; ml = ol; }
            }
            {
                uint32_t ov = __shfl_xor_sync(0xffffffffu, m, 2);
                int      ol = __shfl_xor_sync(0xffffffffu, ml, 2);
                if (ov > m) { m = ov; ml = ol; }
            }
            if (lane == ml) {
                #pragma unroll
                for (int j = 0; j < TOPT - 1; j++) bs[j] = bs[j + 1];
                bs[TOPT - 1] = 0u;
            }
            outv[r] = m;
        }
        if (tsg == 0) {
            int q = (qhalf * QPC + qt) * QT + tq;
            size_t ob = (((size_t)sp * Q_ + q) * NPT + ptile) * TOPT;
            #pragma unroll
            for (int r = 0; r < TOPT; r++) g_cand[ob + r] = outv[r];
        }
        __syncthreads();   // all sSh reads done before restaging A

        // ---- restage A for next qtile ----
        if (qt < QPC - 1) {
            const __half* src = g_qvech + (size_t)(qhalf * QPC + qt + 1) * QT * D_;
            #pragma unroll
            for (int it = 0; it < 8; it++) {
                int i = tid + it * 512;
                int row = i >> 5, ch = i & 31;
                cp_async16(sbase + swz(row, ch), src + (size_t)row * D_ + ch * 8);
            }
            cp_commit_wait();
            __syncthreads();
        }
    }
}

// ============================================================
// Kernel 2: one block per q; all 4 sp fused.
// 4 parallel tournaments -> 4 x top-32 approx, 128-candidate
// exact f32 rescore (4 independent acc chains for MLP),
// 4 parallel top-11, merge -> top-10, write output.
// grid 1024, block 512
// ============================================================
__global__ __launch_bounds__(512) void select_kernel(const float* __restrict__ ent,
                                                     float* __restrict__ out) {
    __shared__ uint32_t cp_t[S_][TOPT][NPT];   // [sp][rank][list]  16 KB
    __shared__ float    sqv[D_];               // qvec row, 1 KB
    __shared__ int      sel_ix[S_ * MSEL];     // 128 candidates
    __shared__ float    fsc[S_ * MSEL];
    __shared__ float    bsc[S_][NB];
    __shared__ int      bix[S_][NB];

    const int tid = threadIdx.x;
    const int q = blockIdx.x;
    const int wid = tid >> 5, lane = tid & 31;

    // ---- load candidates (all 4 sp) + qvec row ----
    for (int e = tid; e < S_ * NPT * TOPT; e += 512) {
        int sp = e >> 10, r = e & 1023;
        cp_t[sp][r & 7][r >> 3] = g_cand[((size_t)sp * Q_ + q) * (NPT * TOPT) + r];
    }
    for (int i = tid; i < D_; i += 512)
        sqv[i] = g_qvec[q * D_ + i];
    __syncthreads();

    // ---- warps 0-3: parallel tournaments (one per sp) ----
    if (wid < S_) {
        const int sp = wid;
        int      h[4];
        uint32_t hv[4];
        #pragma unroll
        for (int j = 0; j < 4; j++) { h[j] = 0; hv[j] = cp_t[sp][0][lane * 4 + j]; }
        for (int r = 0; r < MSEL; r++) {
            uint32_t best = hv[0]; int bj = 0;
            #pragma unroll
            for (int j = 1; j < 4; j++) if (hv[j] > best) { best = hv[j]; bj = j; }
            uint32_t bv = best; int bl = lane;
            #pragma unroll
            for (int off = 16; off > 0; off >>= 1) {
                uint32_t ov = __shfl_down_sync(0xffffffffu, bv, off);
                int      ol = __shfl_down_sync(0xffffffffu, bl, off);
                if (ov > bv) { bv = ov; bl = ol; }
            }
            bl = __shfl_sync(0xffffffffu, bl, 0);
            if (lane == bl) {
                int list = lane * 4 + bj;
                sel_ix[sp * MSEL + r] = (int)(hv[bj] & 0xFFFFu);
                h[bj]++;
                hv[bj] = (h[bj] < TOPT) ? cp_t[sp][h[bj]][list] : 0u;
            }
            __syncwarp();
        }
    }
    __syncthreads();

    // ---- exact f32 rescore: 4 threads/candidate, 4 acc chains ----
    {
        int c = tid >> 2, part = tid & 3;
        int sp = c >> 5;
        int p = sel_ix[c];
        const float4* qv = (const float4*)sqv + part * 16;
        const float4* ev = (const float4*)(ent + ((size_t)sp * P_ + p) * D_) + part * 16;
        float acc[4] = {0.f, 0.f, 0.f, 0.f};
        #pragma unroll
        for (int i = 0; i < 16; i++) {
            float4 a = qv[i], e = ev[i];
            acc[i & 3] = fmaf(a.x, e.x, fmaf(a.y, e.y,
                         fmaf(a.z, e.z, fmaf(a.w, e.w, acc[i & 3]))));
        }
        float accv = (acc[0] + acc[1]) + (acc[2] + acc[3]);
        accv += __shfl_down_sync(0xffffffffu, accv, 2, 4);
        accv += __shfl_down_sync(0xffffffffu, accv, 1, 4);
        if (part == 0) fsc[c] = accv;
    }
    __syncthreads();

    // ---- warps 0-3: parallel exact top-11 of 32 (one per sp) ----
    if (wid < S_) {
        const int sp = wid;
        float v = fsc[sp * MSEL + lane];
        int  ix = sel_ix[sp * MSEL + lane];
        for (int r = 0; r < NB; r++) {
            float bv = v; int bl = lane;
            #pragma unroll
            for (int off = 16; off > 0; off >>= 1) {
                float ov = __shfl_down_sync(0xffffffffu, bv, off);
                int   ol = __shfl_down_sync(0xffffffffu, bl, off);
                if (ov > bv) { bv = ov; bl = ol; }
            }
            bl = __shfl_sync(0xffffffffu, bl, 0);
            float wv = __shfl_sync(0xffffffffu, v, bl);
            int   wi = __shfl_sync(0xffffffffu, ix, bl);
            if (lane == 0) { bsc[sp][r] = wv; bix[sp][r] = wi; }
            if (lane == bl) v = NEG_INF;
            __syncwarp();
        }
    }
    __syncthreads();

    // ---- thread 0: 4-way sorted merge -> top-10, write output ----
    if (tid == 0) {
        int h0 = 0, h1 = 0, h2 = 0, h3 = 0;
        #pragma unroll
        for (int k = 0; k < KOUT; k++) {
            float best = NEG_INF; int bsp = 0;
            #define TRYS(spv, h) { float v = ((h) < NB) ? bsc[spv][h] : NEG_INF; \
                                   if (v > best) { best = v; bsp = (spv); } }
            TRYS(0, h0) TRYS(1, h1) TRYS(2, h2) TRYS(3, h3)
            #undef TRYS
            int hh = (bsp == 0) ? h0 : (bsp == 1) ? h1 : (bsp == 2) ? h2 : h3;
            int gid = bix[bsp][hh] * S_ + bsp;
            out[q * KOUT + k]             = (float)gid;
            out[Q_ * KOUT + q * KOUT + k] = best;
            if      (bsp == 0) h0++;
            else if (bsp == 1) h1++;
            else if (bsp == 2) h2++;
            else               h3++;
        }
    }
}

// ============================================================
extern "C" void kernel_launch(void* const* d_in, const int* in_sizes, int n_in,
                              void* d_out, int out_size) {
    const int*   relation = (const int*)d_in[0];
    const int*   head     = (const int*)d_in[1];
    const float* ent      = (const float*)d_in[2];
    const float* rel      = (const float*)d_in[3];
    float* out = (float*)d_out;

    cudaFuncSetAttribute(score_kernel, cudaFuncAttributeMaxDynamicSharedMemorySize, SM_TOTAL);

    qvec_kernel<<<Q_, D_>>>(relation, head, ent, rel);
    dim3 g1(2, NPT, S_);
    score_kernel<<<g1, 512, SM_TOTAL>>>(ent);
    select_kernel<<<Q_, 512>>>(ent, out);
}